// round 1
// baseline (speedup 1.0000x reference)
#include <cuda_runtime.h>
#include <cstdint>

// ---------------------------------------------------------------------------
// Problem: B=64, L=512, Din=256, Dout=256, split=128
//   G = inp @ [Wr|Wz|Wh] + [br|bz|bh]     (precomputed, [B*L][768])
//   a = sigmoid(x@(k1-k2))                (precomputed, [B*L])
//   recurrence per (b):  mt -> S = mt@[Ur|Uz|Uh] -> gates -> h
// ---------------------------------------------------------------------------

#define B_  64
#define L_  512
#define D_  256

// scratch (static device globals: allowed, no runtime allocation)
__device__ float g_G[(size_t)B_ * L_ * 768];     // ~100.7 MB
__device__ float g_A[(size_t)B_ * L_];           // 128 KB
__device__ float g_hist[(size_t)L_ * B_ * 128];  // upper half of h history, 16 MB

// ---------------------------------------------------------------------------
// Kernel 1: precompute G = inp @ Wcat + bias.  128x128x16 fp32 SGEMM tiles.
// grid (6, 256), 256 threads. ntile -> gate = ntile/2, ncol0 = (ntile&1)*128
// ---------------------------------------------------------------------------
__global__ void __launch_bounds__(256) gemm_pre(
    const float* __restrict__ inp,
    const float* __restrict__ Wr, const float* __restrict__ Wz, const float* __restrict__ Wh,
    const float* __restrict__ br, const float* __restrict__ bz, const float* __restrict__ bh)
{
    __shared__ float As[16][132];   // A transposed [k][m], padded
    __shared__ float Bs[16][128];   // [k][n]

    const int ntile = blockIdx.x;
    const int mtile = blockIdx.y;
    const int gate  = ntile >> 1;
    const int ncol0 = (ntile & 1) * 128;
    const float* W    = (gate == 0) ? Wr : (gate == 1) ? Wz : Wh;
    const float* bias = (gate == 0) ? br : (gate == 1) ? bz : bh;

    const int tid = threadIdx.x;
    const int tm  = (tid >> 4) * 8;       // 0..120
    const int tn  = (tid & 15) * 8;       // 0..120

    const float* Ag = inp + (size_t)mtile * 128 * D_;
    const float* Bg = W + ncol0;

    const int a_row = tid >> 2;           // 0..63
    const int a_col = (tid & 3) * 4;      // 0,4,8,12
    const int b_row = tid >> 5;           // 0..7
    const int b_col = (tid & 31) * 4;     // 0..124

    float acc[8][8];
#pragma unroll
    for (int i = 0; i < 8; ++i)
#pragma unroll
        for (int jj = 0; jj < 8; ++jj) acc[i][jj] = 0.f;

    for (int k0 = 0; k0 < D_; k0 += 16) {
        float4 a0  = *(const float4*)(Ag + (size_t)a_row        * D_ + k0 + a_col);
        float4 a1  = *(const float4*)(Ag + (size_t)(a_row + 64) * D_ + k0 + a_col);
        float4 bv0 = *(const float4*)(Bg + (size_t)(k0 + b_row)     * D_ + b_col);
        float4 bv1 = *(const float4*)(Bg + (size_t)(k0 + b_row + 8) * D_ + b_col);

        __syncthreads();
        As[a_col + 0][a_row] = a0.x; As[a_col + 1][a_row] = a0.y;
        As[a_col + 2][a_row] = a0.z; As[a_col + 3][a_row] = a0.w;
        As[a_col + 0][a_row + 64] = a1.x; As[a_col + 1][a_row + 64] = a1.y;
        As[a_col + 2][a_row + 64] = a1.z; As[a_col + 3][a_row + 64] = a1.w;
        *(float4*)&Bs[b_row][b_col]     = bv0;
        *(float4*)&Bs[b_row + 8][b_col] = bv1;
        __syncthreads();

#pragma unroll
        for (int k = 0; k < 16; ++k) {
            float4 af0 = *(const float4*)&As[k][tm];
            float4 af1 = *(const float4*)&As[k][tm + 4];
            float4 bf0 = *(const float4*)&Bs[k][tn];
            float4 bf1 = *(const float4*)&Bs[k][tn + 4];
            float am[8] = {af0.x, af0.y, af0.z, af0.w, af1.x, af1.y, af1.z, af1.w};
            float bn[8] = {bf0.x, bf0.y, bf0.z, bf0.w, bf1.x, bf1.y, bf1.z, bf1.w};
#pragma unroll
            for (int i = 0; i < 8; ++i)
#pragma unroll
                for (int jj = 0; jj < 8; ++jj) acc[i][jj] += am[i] * bn[jj];
        }
    }

    float bb[8];
#pragma unroll
    for (int jj = 0; jj < 8; ++jj) bb[jj] = bias[ncol0 + tn + jj];

    const size_t ng0 = (size_t)gate * 256 + ncol0 + tn;
#pragma unroll
    for (int i = 0; i < 8; ++i) {
        size_t m = (size_t)mtile * 128 + tm + i;
        float4 o0 = make_float4(acc[i][0] + bb[0], acc[i][1] + bb[1],
                                acc[i][2] + bb[2], acc[i][3] + bb[3]);
        float4 o1 = make_float4(acc[i][4] + bb[4], acc[i][5] + bb[5],
                                acc[i][6] + bb[6], acc[i][7] + bb[7]);
        *(float4*)&g_G[m * 768 + ng0]     = o0;
        *(float4*)&g_G[m * 768 + ng0 + 4] = o1;
    }
}

// ---------------------------------------------------------------------------
// Kernel 2: a[m] = sigmoid(x[m] . (k1 - k2)).  One warp per row.
// ---------------------------------------------------------------------------
__global__ void __launch_bounds__(256) avals_kernel(
    const float* __restrict__ inp,
    const float* __restrict__ k1, const float* __restrict__ k2)
{
    const int warp = threadIdx.x >> 5, lane = threadIdx.x & 31;
    const int m = blockIdx.x * 8 + warp;
    const float* x = inp + (size_t)m * D_;
    float s = 0.f;
#pragma unroll
    for (int i = lane; i < D_; i += 32) s += x[i] * (k1[i] - k2[i]);
#pragma unroll
    for (int o = 16; o; o >>= 1) s += __shfl_xor_sync(0xFFFFFFFFu, s, o);
    if (lane == 0) g_A[m] = 1.f / (1.f + __expf(-s));
}

// ---------------------------------------------------------------------------
// Kernel 3: recurrence. 32 clusters x 4 CTAs. Cluster handles b0=2g, b0+1.
// CTA rank r owns output columns [64r, 64r+64); Ur/Uz/Uh slices resident in smem.
// ---------------------------------------------------------------------------
__device__ __forceinline__ unsigned smem_u32(const void* p) {
    unsigned a;
    asm("{ .reg .u64 t; cvta.to.shared.u64 t, %1; cvt.u32.u64 %0, t; }" : "=r"(a) : "l"(p));
    return a;
}

__global__ void __launch_bounds__(256, 1) __cluster_dims__(4, 1, 1)
recur_kernel(const float* __restrict__ Ur, const float* __restrict__ Uz,
             const float* __restrict__ Uh, const int* __restrict__ ci,
             float* __restrict__ out)
{
    extern __shared__ float smf[];
    float* Us   = smf;                 // [3][256][64]   = 49152 floats
    float* mts  = Us + 3 * 256 * 64;   // [2][256]       = 512
    float* hbuf = mts + 512;           // [2][2][128]    = 512 (phase, b, d<128)
    float* part = hbuf + 512;          // [4][3][2][64]  = 1536

    const int tid  = threadIdx.x;
    const int rank = blockIdx.x & 3;
    const int grp  = blockIdx.x >> 2;
    const int b0   = grp * 2;
    const int dg0  = rank * 64;

    // load resident U slices: Us[g][k][j] = Ug[k*256 + dg0 + j]
    {
        const float* Ug[3] = {Ur, Uz, Uh};
#pragma unroll
        for (int g = 0; g < 3; ++g)
            for (int i = tid; i < 256 * 16; i += 256) {
                int k = i >> 4, q = (i & 15) * 4;
                *(float4*)&Us[g * 16384 + k * 64 + q] =
                    *(const float4*)(Ug[g] + (size_t)k * D_ + dg0 + q);
            }
    }
    for (int i = tid; i < 512; i += 256) hbuf[i] = 0.f;   // zero both phases
    __syncthreads();
    asm volatile("barrier.cluster.arrive.aligned;" ::: "memory");
    asm volatile("barrier.cluster.wait.aligned;" ::: "memory");

    // roles
    const int j  = tid & 63;          // GEMM column
    const int kq = tid >> 6;          // GEMM k-quarter
    const int eb = tid >> 6;          // eltwise b (tid<128)
    const int ej = tid & 63;
    const int dg = dg0 + ej;
    const int mb = tid >> 7;          // mt-build b
    const int mk = (tid & 127) * 2;   // mt-build k (pair)

    // prefetch G for t=0 (tid<128)
    float gn0 = 0.f, gn1 = 0.f, gn2 = 0.f;
    if (tid < 128) {
        size_t gb = ((size_t)(b0 + eb) * L_ + 0) * 768 + dg;
        gn0 = g_G[gb]; gn1 = g_G[gb + 256]; gn2 = g_G[gb + 512];
    }

    for (int t = 0; t < L_; ++t) {
        const int p = t & 1;

        // ---- build mt[2][256]
        {
            float av = g_A[(size_t)(b0 + mb) * L_ + t];
            float v0, v1;
            if (mk < 128) {
                v0 = av * hbuf[(p * 2 + mb) * 128 + mk];
                v1 = av * hbuf[(p * 2 + mb) * 128 + mk + 1];
            } else {
                int c = ci[(size_t)(b0 + mb) * L_ + t];
                if (c > 0) {
                    const float* hp = &g_hist[(((size_t)(c - 1)) * B_ + b0 + mb) * 128 + (mk - 128)];
                    float om = 1.f - av;
                    v0 = om * hp[0]; v1 = om * hp[1];
                } else { v0 = 0.f; v1 = 0.f; }
            }
            mts[mb * 256 + mk]     = v0;
            mts[mb * 256 + mk + 1] = v1;
        }
        __syncthreads();

        // ---- split-K GEMM: S[g][b][j], partial over kq
        float a00 = 0.f, a01 = 0.f, a10 = 0.f, a11 = 0.f, a20 = 0.f, a21 = 0.f;
        {
            const float* u0  = &Us[0 * 16384 + (kq * 64) * 64 + j];
            const float* u1  = u0 + 16384;
            const float* u2  = u1 + 16384;
            const float* m0p = &mts[kq * 64];
            const float* m1p = &mts[256 + kq * 64];
#pragma unroll
            for (int kk = 0; kk < 64; kk += 4) {
                float4 m0 = *(const float4*)(m0p + kk);
                float4 m1 = *(const float4*)(m1p + kk);
                float mm0[4] = {m0.x, m0.y, m0.z, m0.w};
                float mm1[4] = {m1.x, m1.y, m1.z, m1.w};
#pragma unroll
                for (int q = 0; q < 4; ++q) {
                    float uu0 = u0[(kk + q) * 64];
                    float uu1 = u1[(kk + q) * 64];
                    float uu2 = u2[(kk + q) * 64];
                    a00 += mm0[q] * uu0; a01 += mm1[q] * uu0;
                    a10 += mm0[q] * uu1; a11 += mm1[q] * uu1;
                    a20 += mm0[q] * uu2; a21 += mm1[q] * uu2;
                }
            }
        }
        part[((kq * 3 + 0) * 2 + 0) * 64 + j] = a00;
        part[((kq * 3 + 0) * 2 + 1) * 64 + j] = a01;
        part[((kq * 3 + 1) * 2 + 0) * 64 + j] = a10;
        part[((kq * 3 + 1) * 2 + 1) * 64 + j] = a11;
        part[((kq * 3 + 2) * 2 + 0) * 64 + j] = a20;
        part[((kq * 3 + 2) * 2 + 1) * 64 + j] = a21;
        __syncthreads();

        // ---- elementwise (tid < 128): one (b, column) each
        if (tid < 128) {
            float Sr = 0.f, Sz = 0.f, Sh = 0.f;
#pragma unroll
            for (int q = 0; q < 4; ++q) {
                Sr += part[((q * 3 + 0) * 2 + eb) * 64 + ej];
                Sz += part[((q * 3 + 1) * 2 + eb) * 64 + ej];
                Sh += part[((q * 3 + 2) * 2 + eb) * 64 + ej];
            }
            float r  = 1.f / (1.f + __expf(-(gn0 + Sr)));
            float z  = 1.f / (1.f + __expf(-(gn1 + Sz)));
            float ti = gn2 + r * Sh;
            float th = 2.f / (1.f + __expf(-2.f * ti)) - 1.f;
            float mtd = mts[eb * 256 + dg];
            float h = (1.f - z) * mtd + z * th;

            out[(((size_t)(b0 + eb)) * L_ + t) * D_ + dg] = h;
            if (dg >= 128) {
                g_hist[((size_t)t * B_ + b0 + eb) * 128 + dg - 128] = h;
            } else {
                // broadcast h (lower half) to all 4 cluster CTAs, phase p^1
                unsigned laddr = smem_u32(&hbuf[((p ^ 1) * 2 + eb) * 128 + dg]);
#pragma unroll
                for (int rr = 0; rr < 4; ++rr)
                    asm volatile(
                        "{ .reg .b32 ra; mapa.shared::cluster.u32 ra, %0, %1;"
                        "  st.shared::cluster.f32 [ra], %2; }"
                        :: "r"(laddr), "r"(rr), "f"(h));
            }
            // prefetch G for next step
            int tn = (t + 1 < L_) ? (t + 1) : (L_ - 1);
            size_t gb = ((size_t)(b0 + eb) * L_ + tn) * 768 + dg;
            gn0 = g_G[gb]; gn1 = g_G[gb + 256]; gn2 = g_G[gb + 512];
        }

        asm volatile("barrier.cluster.arrive.aligned;" ::: "memory");
        asm volatile("barrier.cluster.wait.aligned;" ::: "memory");
    }
}

// ---------------------------------------------------------------------------
// launch
// ---------------------------------------------------------------------------
extern "C" void kernel_launch(void* const* d_in, const int* in_sizes, int n_in,
                              void* d_out, int out_size)
{
    const float* inp = (const float*)d_in[0];
    const int*   ci  = (const int*)  d_in[1];
    const float* Wr  = (const float*)d_in[2];
    const float* br  = (const float*)d_in[3];
    const float* Ur  = (const float*)d_in[4];
    const float* Wz  = (const float*)d_in[5];
    const float* bz  = (const float*)d_in[6];
    const float* Uz  = (const float*)d_in[7];
    const float* Wh  = (const float*)d_in[8];
    const float* bh  = (const float*)d_in[9];
    const float* Uh  = (const float*)d_in[10];
    const float* k1  = (const float*)d_in[11];
    const float* k2  = (const float*)d_in[12];
    float* out = (float*)d_out;

    // precompute G and a
    gemm_pre<<<dim3(6, (B_ * L_) / 128), 256>>>(inp, Wr, Wz, Wh, br, bz, bh);
    avals_kernel<<<(B_ * L_) / 8, 256>>>(inp, k1, k2);

    // recurrence
    const int smem = (3 * 256 * 64 + 512 + 512 + 1536) * (int)sizeof(float); // 206848
    static_assert((3 * 256 * 64 + 512 + 512 + 1536) * 4 == 206848, "smem");
    cudaFuncSetAttribute(recur_kernel, cudaFuncAttributeMaxDynamicSharedMemorySize, smem);
    recur_kernel<<<128, 256, smem>>>(Ur, Uz, Uh, ci, out);
}

// round 2
// speedup vs baseline: 1.1751x; 1.1751x over previous
#include <cuda_runtime.h>
#include <cstdint>

// ---------------------------------------------------------------------------
// Problem: B=64, L=512, Din=256, Dout=256, split=128
//   G = inp @ [Wr|Wz|Wh] + [br|bz|bh]     (precomputed, [B*L][768])
//   a = sigmoid(x@(k1-k2))                (precomputed, [B*L])
//   recurrence per (b):  mt -> S = mt@[Ur|Uz|Uh] -> gates -> h
// Recurrence: 32 clusters x 4 CTAs; U held in REGISTERS (f32x2 packed FMA).
// ---------------------------------------------------------------------------

#define B_  64
#define L_  512
#define D_  256

__device__ float g_G[(size_t)B_ * L_ * 768];     // ~100.7 MB
__device__ float g_A[(size_t)B_ * L_];           // 128 KB
__device__ float g_hist[(size_t)L_ * B_ * 128];  // upper half of h history, 16 MB

// ---------------------------------------------------------------------------
// packed f32x2 helpers
// ---------------------------------------------------------------------------
__device__ __forceinline__ unsigned long long ffma2(
    unsigned long long a, unsigned long long b, unsigned long long c)
{
    unsigned long long d;
    asm("fma.rn.f32x2 %0, %1, %2, %3;" : "=l"(d) : "l"(a), "l"(b), "l"(c));
    return d;
}
__device__ __forceinline__ unsigned long long pack2(float x, float y) {
    unsigned long long r;
    asm("mov.b64 %0, {%1, %2};" : "=l"(r) : "f"(x), "f"(y));
    return r;
}
__device__ __forceinline__ float hadd2(unsigned long long v) {
    float x, y;
    asm("mov.b64 {%0, %1}, %2;" : "=f"(x), "=f"(y) : "l"(v));
    return x + y;
}
__device__ __forceinline__ unsigned smem_u32(const void* p) {
    unsigned a;
    asm("{ .reg .u64 t; cvta.to.shared.u64 t, %1; cvt.u32.u64 %0, t; }" : "=r"(a) : "l"(p));
    return a;
}

// ---------------------------------------------------------------------------
// Kernel 1: precompute G = inp @ Wcat + bias.  128x128x16 fp32 SGEMM tiles.
// ---------------------------------------------------------------------------
__global__ void __launch_bounds__(256) gemm_pre(
    const float* __restrict__ inp,
    const float* __restrict__ Wr, const float* __restrict__ Wz, const float* __restrict__ Wh,
    const float* __restrict__ br, const float* __restrict__ bz, const float* __restrict__ bh)
{
    __shared__ float As[16][132];   // A transposed [k][m], padded
    __shared__ float Bs[16][128];   // [k][n]

    const int ntile = blockIdx.x;
    const int mtile = blockIdx.y;
    const int gate  = ntile >> 1;
    const int ncol0 = (ntile & 1) * 128;
    const float* W    = (gate == 0) ? Wr : (gate == 1) ? Wz : Wh;
    const float* bias = (gate == 0) ? br : (gate == 1) ? bz : bh;

    const int tid = threadIdx.x;
    const int tm  = (tid >> 4) * 8;
    const int tn  = (tid & 15) * 8;

    const float* Ag = inp + (size_t)mtile * 128 * D_;
    const float* Bg = W + ncol0;

    const int a_row = tid >> 2;
    const int a_col = (tid & 3) * 4;
    const int b_row = tid >> 5;
    const int b_col = (tid & 31) * 4;

    float acc[8][8];
#pragma unroll
    for (int i = 0; i < 8; ++i)
#pragma unroll
        for (int jj = 0; jj < 8; ++jj) acc[i][jj] = 0.f;

    for (int k0 = 0; k0 < D_; k0 += 16) {
        float4 a0  = *(const float4*)(Ag + (size_t)a_row        * D_ + k0 + a_col);
        float4 a1  = *(const float4*)(Ag + (size_t)(a_row + 64) * D_ + k0 + a_col);
        float4 bv0 = *(const float4*)(Bg + (size_t)(k0 + b_row)     * D_ + b_col);
        float4 bv1 = *(const float4*)(Bg + (size_t)(k0 + b_row + 8) * D_ + b_col);

        __syncthreads();
        As[a_col + 0][a_row] = a0.x; As[a_col + 1][a_row] = a0.y;
        As[a_col + 2][a_row] = a0.z; As[a_col + 3][a_row] = a0.w;
        As[a_col + 0][a_row + 64] = a1.x; As[a_col + 1][a_row + 64] = a1.y;
        As[a_col + 2][a_row + 64] = a1.z; As[a_col + 3][a_row + 64] = a1.w;
        *(float4*)&Bs[b_row][b_col]     = bv0;
        *(float4*)&Bs[b_row + 8][b_col] = bv1;
        __syncthreads();

#pragma unroll
        for (int k = 0; k < 16; ++k) {
            float4 af0 = *(const float4*)&As[k][tm];
            float4 af1 = *(const float4*)&As[k][tm + 4];
            float4 bf0 = *(const float4*)&Bs[k][tn];
            float4 bf1 = *(const float4*)&Bs[k][tn + 4];
            float am[8] = {af0.x, af0.y, af0.z, af0.w, af1.x, af1.y, af1.z, af1.w};
            float bn[8] = {bf0.x, bf0.y, bf0.z, bf0.w, bf1.x, bf1.y, bf1.z, bf1.w};
#pragma unroll
            for (int i = 0; i < 8; ++i)
#pragma unroll
                for (int jj = 0; jj < 8; ++jj) acc[i][jj] += am[i] * bn[jj];
        }
    }

    float bb[8];
#pragma unroll
    for (int jj = 0; jj < 8; ++jj) bb[jj] = bias[ncol0 + tn + jj];

    const size_t ng0 = (size_t)gate * 256 + ncol0 + tn;
#pragma unroll
    for (int i = 0; i < 8; ++i) {
        size_t m = (size_t)mtile * 128 + tm + i;
        float4 o0 = make_float4(acc[i][0] + bb[0], acc[i][1] + bb[1],
                                acc[i][2] + bb[2], acc[i][3] + bb[3]);
        float4 o1 = make_float4(acc[i][4] + bb[4], acc[i][5] + bb[5],
                                acc[i][6] + bb[6], acc[i][7] + bb[7]);
        *(float4*)&g_G[m * 768 + ng0]     = o0;
        *(float4*)&g_G[m * 768 + ng0 + 4] = o1;
    }
}

// ---------------------------------------------------------------------------
// Kernel 2: a[m] = sigmoid(x[m] . (k1 - k2)).
// ---------------------------------------------------------------------------
__global__ void __launch_bounds__(256) avals_kernel(
    const float* __restrict__ inp,
    const float* __restrict__ k1, const float* __restrict__ k2)
{
    const int warp = threadIdx.x >> 5, lane = threadIdx.x & 31;
    const int m = blockIdx.x * 8 + warp;
    const float* x = inp + (size_t)m * D_;
    float s = 0.f;
#pragma unroll
    for (int i = lane; i < D_; i += 32) s += x[i] * (k1[i] - k2[i]);
#pragma unroll
    for (int o = 16; o; o >>= 1) s += __shfl_xor_sync(0xFFFFFFFFu, s, o);
    if (lane == 0) g_A[m] = 1.f / (1.f + __expf(-s));
}

// ---------------------------------------------------------------------------
// Kernel 3: recurrence. 32 clusters x 4 CTAs; cluster handles b0=2g, b0+1.
// CTA rank r owns output cols [64r,64r+64). U lives in per-thread REGISTERS:
// thread (kq=tid>>6, j=tid&63) owns U{r,z,h}[kq*64 .. kq*64+64)[dg0+j]
// as 96 packed f32x2 registers. GEMM = 192 fma.rn.f32x2 / thread / step.
// ---------------------------------------------------------------------------
__global__ void __launch_bounds__(256, 1) __cluster_dims__(4, 1, 1)
recur_kernel(const float* __restrict__ Ur, const float* __restrict__ Uz,
             const float* __restrict__ Uh, const int* __restrict__ ci,
             float* __restrict__ out)
{
    __shared__ __align__(16) float mts[2 * 256];        // [b][k]
    __shared__ __align__(16) float hbuf[2 * 2 * 128];   // [phase][b][d<128]
    __shared__ __align__(16) float part[4 * 3 * 2 * 64];// [kq][g][b][j]

    const int tid  = threadIdx.x;
    const int rank = blockIdx.x & 3;
    const int grp  = blockIdx.x >> 2;
    const int b0   = grp * 2;
    const int dg0  = rank * 64;

    const int j  = tid & 63;          // GEMM column
    const int kq = tid >> 6;          // GEMM k-quarter
    const int k0 = kq * 64;

    // ---- load U slice into registers (one-time) ----
    unsigned long long u0[32], u1[32], u2[32];
    {
        const float* pr = Ur + (size_t)k0 * D_ + dg0 + j;
        const float* pz = Uz + (size_t)k0 * D_ + dg0 + j;
        const float* ph = Uh + (size_t)k0 * D_ + dg0 + j;
#pragma unroll
        for (int i = 0; i < 32; ++i) {
            u0[i] = pack2(pr[(2 * i) * D_], pr[(2 * i + 1) * D_]);
            u1[i] = pack2(pz[(2 * i) * D_], pz[(2 * i + 1) * D_]);
            u2[i] = pack2(ph[(2 * i) * D_], ph[(2 * i + 1) * D_]);
        }
    }

    for (int i = tid; i < 512; i += 256) hbuf[i] = 0.f;
    __syncthreads();
    asm volatile("barrier.cluster.arrive.aligned;" ::: "memory");
    asm volatile("barrier.cluster.wait.aligned;" ::: "memory");

    // roles for other phases
    const int eb = tid >> 6;          // eltwise b (tid<128)
    const int ej = tid & 63;
    const int dg = dg0 + ej;
    const int mb = tid >> 7;          // mt-build b
    const int mk = (tid & 127) * 2;   // mt-build k (pair)

    // prefetch G for t=0 (tid<128)
    float gn0 = 0.f, gn1 = 0.f, gn2 = 0.f;
    if (tid < 128) {
        size_t gb = ((size_t)(b0 + eb) * L_ + 0) * 768 + dg;
        gn0 = g_G[gb]; gn1 = g_G[gb + 256]; gn2 = g_G[gb + 512];
    }

    for (int t = 0; t < L_; ++t) {
        const int p = t & 1;

        // ---- build mt[2][256]
        {
            float av = g_A[(size_t)(b0 + mb) * L_ + t];
            float v0, v1;
            if (mk < 128) {
                v0 = av * hbuf[(p * 2 + mb) * 128 + mk];
                v1 = av * hbuf[(p * 2 + mb) * 128 + mk + 1];
            } else {
                int c = ci[(size_t)(b0 + mb) * L_ + t];
                if (c > 0) {
                    const float* hp = &g_hist[(((size_t)(c - 1)) * B_ + b0 + mb) * 128 + (mk - 128)];
                    float om = 1.f - av;
                    v0 = om * hp[0]; v1 = om * hp[1];
                } else { v0 = 0.f; v1 = 0.f; }
            }
            mts[mb * 256 + mk]     = v0;
            mts[mb * 256 + mk + 1] = v1;
        }
        __syncthreads();

        // ---- GEMM: registers x smem-broadcast mt, packed f32x2
        unsigned long long a00 = 0ull, a01 = 0ull;   // gate r, b0/b1
        unsigned long long a10 = 0ull, a11 = 0ull;   // gate z
        unsigned long long a20 = 0ull, a21 = 0ull;   // gate h
        {
            const ulonglong2* m0 = (const ulonglong2*)&mts[k0];
            const ulonglong2* m1 = (const ulonglong2*)&mts[256 + k0];
#pragma unroll
            for (int i = 0; i < 16; ++i) {
                ulonglong2 v0 = m0[i];   // two packed k-pairs, b=0
                ulonglong2 v1 = m1[i];   // b=1
                a00 = ffma2(u0[2 * i], v0.x, a00);
                a01 = ffma2(u0[2 * i], v1.x, a01);
                a10 = ffma2(u1[2 * i], v0.x, a10);
                a11 = ffma2(u1[2 * i], v1.x, a11);
                a20 = ffma2(u2[2 * i], v0.x, a20);
                a21 = ffma2(u2[2 * i], v1.x, a21);
                a00 = ffma2(u0[2 * i + 1], v0.y, a00);
                a01 = ffma2(u0[2 * i + 1], v1.y, a01);
                a10 = ffma2(u1[2 * i + 1], v0.y, a10);
                a11 = ffma2(u1[2 * i + 1], v1.y, a11);
                a20 = ffma2(u2[2 * i + 1], v0.y, a20);
                a21 = ffma2(u2[2 * i + 1], v1.y, a21);
            }
        }
        part[((kq * 3 + 0) * 2 + 0) * 64 + j] = hadd2(a00);
        part[((kq * 3 + 0) * 2 + 1) * 64 + j] = hadd2(a01);
        part[((kq * 3 + 1) * 2 + 0) * 64 + j] = hadd2(a10);
        part[((kq * 3 + 1) * 2 + 1) * 64 + j] = hadd2(a11);
        part[((kq * 3 + 2) * 2 + 0) * 64 + j] = hadd2(a20);
        part[((kq * 3 + 2) * 2 + 1) * 64 + j] = hadd2(a21);
        __syncthreads();

        // ---- elementwise (tid < 128): one (b, column) each
        if (tid < 128) {
            float Sr = 0.f, Sz = 0.f, Sh = 0.f;
#pragma unroll
            for (int q = 0; q < 4; ++q) {
                Sr += part[((q * 3 + 0) * 2 + eb) * 64 + ej];
                Sz += part[((q * 3 + 1) * 2 + eb) * 64 + ej];
                Sh += part[((q * 3 + 2) * 2 + eb) * 64 + ej];
            }
            float r  = 1.f / (1.f + __expf(-(gn0 + Sr)));
            float z  = 1.f / (1.f + __expf(-(gn1 + Sz)));
            float ti = gn2 + r * Sh;
            float th = 2.f / (1.f + __expf(-2.f * ti)) - 1.f;
            float mtd = mts[eb * 256 + dg];
            float h = (1.f - z) * mtd + z * th;

            out[(((size_t)(b0 + eb)) * L_ + t) * D_ + dg] = h;
            if (dg >= 128) {
                g_hist[((size_t)t * B_ + b0 + eb) * 128 + dg - 128] = h;
            } else {
                unsigned laddr = smem_u32(&hbuf[((p ^ 1) * 2 + eb) * 128 + dg]);
#pragma unroll
                for (int rr = 0; rr < 4; ++rr)
                    asm volatile(
                        "{ .reg .b32 ra; mapa.shared::cluster.u32 ra, %0, %1;"
                        "  st.shared::cluster.f32 [ra], %2; }"
                        :: "r"(laddr), "r"(rr), "f"(h));
            }
            int tn = (t + 1 < L_) ? (t + 1) : (L_ - 1);
            size_t gb = ((size_t)(b0 + eb) * L_ + tn) * 768 + dg;
            gn0 = g_G[gb]; gn1 = g_G[gb + 256]; gn2 = g_G[gb + 512];
        }

        asm volatile("barrier.cluster.arrive.aligned;" ::: "memory");
        asm volatile("barrier.cluster.wait.aligned;" ::: "memory");
    }
}

// ---------------------------------------------------------------------------
// launch
// ---------------------------------------------------------------------------
extern "C" void kernel_launch(void* const* d_in, const int* in_sizes, int n_in,
                              void* d_out, int out_size)
{
    const float* inp = (const float*)d_in[0];
    const int*   ci  = (const int*)  d_in[1];
    const float* Wr  = (const float*)d_in[2];
    const float* br  = (const float*)d_in[3];
    const float* Ur  = (const float*)d_in[4];
    const float* Wz  = (const float*)d_in[5];
    const float* bz  = (const float*)d_in[6];
    const float* Uz  = (const float*)d_in[7];
    const float* Wh  = (const float*)d_in[8];
    const float* bh  = (const float*)d_in[9];
    const float* Uh  = (const float*)d_in[10];
    const float* k1  = (const float*)d_in[11];
    const float* k2  = (const float*)d_in[12];
    float* out = (float*)d_out;

    gemm_pre<<<dim3(6, (B_ * L_) / 128), 256>>>(inp, Wr, Wz, Wh, br, bz, bh);
    avals_kernel<<<(B_ * L_) / 8, 256>>>(inp, k1, k2);
    recur_kernel<<<128, 256>>>(Ur, Uz, Uh, ci, out);
}